// round 2
// baseline (speedup 1.0000x reference)
#include <cuda_runtime.h>
#include <math.h>

// Problem constants
#define BATCH   2
#define SEQ     2048
#define DMODEL  2048
#define NHEADS  16
#define HDIM    128
#define MTOK    (BATCH*SEQ)   // 4096 tokens

// -------------------- scratch (device globals: no cudaMalloc allowed) -----
__device__ float g_Q[(size_t)MTOK*DMODEL];
__device__ float g_K[(size_t)MTOK*DMODEL];
__device__ float g_V[(size_t)MTOK*DMODEL];
__device__ float g_A[(size_t)MTOK*DMODEL];

// ==========================================================================
// GEMM:  C[M,N] = A[M,K] @ W[N,K]^T + bias[N]
// Classic 128x128x8 tile, 256 threads, 8x8 per thread (split 4+4 quads).
// ==========================================================================
#define GBM 128
#define GBN 128
#define GBK 8

__global__ __launch_bounds__(256, 2)
void gemm_xwT_bias(const float* __restrict__ A, const float* __restrict__ W,
                   const float* __restrict__ bias, float* __restrict__ C,
                   int M, int N, int K)
{
    __shared__ float As[GBK][GBM];
    __shared__ float Bs[GBK][GBN];

    const int tid = threadIdx.x;
    const int ty  = tid >> 4;        // 0..15
    const int tx  = tid & 15;        // 0..15
    const int m0  = blockIdx.y * GBM;
    const int n0  = blockIdx.x * GBN;

    const int lr = tid >> 1;         // 0..127
    const int lc = (tid & 1) * 4;    // 0 or 4

    float acc[8][8];
#pragma unroll
    for (int i = 0; i < 8; i++)
#pragma unroll
        for (int j = 0; j < 8; j++) acc[i][j] = 0.0f;

    for (int k0 = 0; k0 < K; k0 += GBK) {
        float4 av = *(const float4*)&A[(size_t)(m0 + lr) * K + k0 + lc];
        float4 wv = *(const float4*)&W[(size_t)(n0 + lr) * K + k0 + lc];
        As[lc + 0][lr] = av.x; As[lc + 1][lr] = av.y;
        As[lc + 2][lr] = av.z; As[lc + 3][lr] = av.w;
        Bs[lc + 0][lr] = wv.x; Bs[lc + 1][lr] = wv.y;
        Bs[lc + 2][lr] = wv.z; Bs[lc + 3][lr] = wv.w;
        __syncthreads();

#pragma unroll
        for (int k = 0; k < GBK; k++) {
            float4 a0 = *(const float4*)&As[k][ty * 4];
            float4 a1 = *(const float4*)&As[k][64 + ty * 4];
            float4 b0 = *(const float4*)&Bs[k][tx * 4];
            float4 b1 = *(const float4*)&Bs[k][64 + tx * 4];
            float a[8] = {a0.x, a0.y, a0.z, a0.w, a1.x, a1.y, a1.z, a1.w};
            float b[8] = {b0.x, b0.y, b0.z, b0.w, b1.x, b1.y, b1.z, b1.w};
#pragma unroll
            for (int i = 0; i < 8; i++)
#pragma unroll
                for (int j = 0; j < 8; j++)
                    acc[i][j] = fmaf(a[i], b[j], acc[i][j]);
        }
        __syncthreads();
    }

    // epilogue: add bias, vectorized stores (cols come in aligned groups of 4)
#pragma unroll
    for (int i = 0; i < 8; i++) {
        int m = m0 + ((i < 4) ? (ty * 4 + i) : (64 + ty * 4 + (i - 4)));
#pragma unroll
        for (int jh = 0; jh < 2; jh++) {
            int n = n0 + ((jh == 0) ? (tx * 4) : (64 + tx * 4));
            float4 o;
            o.x = acc[i][jh * 4 + 0] + bias[n + 0];
            o.y = acc[i][jh * 4 + 1] + bias[n + 1];
            o.z = acc[i][jh * 4 + 2] + bias[n + 2];
            o.w = acc[i][jh * 4 + 3] + bias[n + 3];
            *(float4*)&C[(size_t)m * N + n] = o;
        }
    }
}

// ==========================================================================
// RoPE (in-place on Q and K, token-major [B*S][DMODEL])
// pair (d, d+64) inside each head; angle = pos * 10000^(-2d/128)
// ==========================================================================
__global__ void rope_kernel(float* __restrict__ Q, float* __restrict__ K)
{
    int p = blockIdx.x * blockDim.x + threadIdx.x;
    const int total = MTOK * NHEADS * (HDIM / 2);
    if (p >= total) return;
    int d = p & 63;
    int h = (p >> 6) & (NHEADS - 1);
    int m = p >> 10;               // token index 0..4095
    int s = m & (SEQ - 1);         // position within sequence

    float inv_freq = powf(10000.0f, -(float)(2 * d) / (float)HDIM);
    float ang = (float)s * inv_freq;
    float sn, cs;
    sincosf(ang, &sn, &cs);

    size_t i1 = (size_t)m * DMODEL + h * HDIM + d;
    size_t i2 = i1 + 64;
    float q1 = Q[i1], q2 = Q[i2];
    Q[i1] = q1 * cs - q2 * sn;
    Q[i2] = q1 * sn + q2 * cs;
    float k1 = K[i1], k2 = K[i2];
    K[i1] = k1 * cs - k2 * sn;
    K[i2] = k1 * sn + k2 * cs;
}

// ==========================================================================
// Flash attention (fp32, causal), 64x64 tiles, online softmax.
// Grid: (SEQ/64, NHEADS, BATCH), 256 threads.
// Thread (ty,tx): S rows ty*4..+3, S cols tx*4..+3, O cols tx*8..+7.
// K and V share one smem buffer (K used for scores, then overwritten by V).
// ==========================================================================
#define FBM 64
#define FBN 64
#define QP  132   // Qs row pitch (floats)
#define KP  132   // K/V row pitch
#define PP  68    // P row pitch
#define FLASH_SMEM (((FBM*QP) + (FBN*KP) + (FBM*PP)) * 4)

__global__ __launch_bounds__(256, 2)
void flash_attn(const float* __restrict__ Q, const float* __restrict__ K,
                const float* __restrict__ V, float* __restrict__ O)
{
    extern __shared__ float sm[];
    float* Qs  = sm;
    float* KVs = sm + FBM * QP;
    float* Ps  = KVs + FBN * KP;

    const int tid = threadIdx.x;
    const int ty = tid >> 4, tx = tid & 15;
    const int qt = blockIdx.x, h = blockIdx.y, b = blockIdx.z;
    const int q0 = qt * FBM;
    const float scale = rsqrtf((float)HDIM);

    const size_t base = (size_t)b * SEQ * DMODEL + (size_t)h * HDIM;

    // load Q tile (pre-scaled by 1/sqrt(HDIM))
    for (int idx = tid; idx < FBM * (HDIM / 4); idx += 256) {
        int r  = idx >> 5;
        int d4 = (idx & 31) << 2;
        float4 v = *(const float4*)&Q[base + (size_t)(q0 + r) * DMODEL + d4];
        v.x *= scale; v.y *= scale; v.z *= scale; v.w *= scale;
        *(float4*)&Qs[r * QP + d4] = v;
    }

    float mi[4], li[4], Oc[4][8];
#pragma unroll
    for (int i = 0; i < 4; i++) {
        mi[i] = -INFINITY; li[i] = 0.0f;
#pragma unroll
        for (int j = 0; j < 8; j++) Oc[i][j] = 0.0f;
    }

    for (int kt = 0; kt <= qt; kt++) {
        __syncthreads();   // all P@V reads of previous V done before reload
        // load K tile
        for (int idx = tid; idx < FBN * (HDIM / 4); idx += 256) {
            int r = idx >> 5, d4 = (idx & 31) << 2;
            *(float4*)&KVs[r * KP + d4] =
                *(const float4*)&K[base + (size_t)(kt * FBN + r) * DMODEL + d4];
        }
        __syncthreads();

        // S = Q @ K^T (64x64, k=128)
        float s_acc[4][4];
#pragma unroll
        for (int i = 0; i < 4; i++)
#pragma unroll
            for (int j = 0; j < 4; j++) s_acc[i][j] = 0.0f;

        for (int k4 = 0; k4 < HDIM; k4 += 4) {
            float4 a[4], bb[4];
#pragma unroll
            for (int i = 0; i < 4; i++)
                a[i] = *(const float4*)&Qs[(ty * 4 + i) * QP + k4];
#pragma unroll
            for (int j = 0; j < 4; j++)
                bb[j] = *(const float4*)&KVs[(tx * 4 + j) * KP + k4];
#pragma unroll
            for (int i = 0; i < 4; i++)
#pragma unroll
                for (int j = 0; j < 4; j++)
                    s_acc[i][j] += a[i].x * bb[j].x + a[i].y * bb[j].y
                                 + a[i].z * bb[j].z + a[i].w * bb[j].w;
        }

        // causal mask on the diagonal tile
        if (kt == qt) {
#pragma unroll
            for (int i = 0; i < 4; i++)
#pragma unroll
                for (int j = 0; j < 4; j++)
                    if (tx * 4 + j > ty * 4 + i) s_acc[i][j] = -INFINITY;
        }

        // online softmax update
#pragma unroll
        for (int i = 0; i < 4; i++) {
            float rmax = fmaxf(fmaxf(s_acc[i][0], s_acc[i][1]),
                               fmaxf(s_acc[i][2], s_acc[i][3]));
#pragma unroll
            for (int off = 8; off > 0; off >>= 1)
                rmax = fmaxf(rmax, __shfl_xor_sync(0xffffffffu, rmax, off));
            float mnew = fmaxf(mi[i], rmax);
            float corr = __expf(mi[i] - mnew);
            float rs = 0.0f;
#pragma unroll
            for (int j = 0; j < 4; j++) {
                float pv = __expf(s_acc[i][j] - mnew);
                s_acc[i][j] = pv;
                rs += pv;
            }
#pragma unroll
            for (int off = 8; off > 0; off >>= 1)
                rs += __shfl_xor_sync(0xffffffffu, rs, off);
            li[i] = li[i] * corr + rs;
            mi[i] = mnew;
#pragma unroll
            for (int jj = 0; jj < 8; jj++) Oc[i][jj] *= corr;
            // stage P in smem for the P@V exchange
            *(float4*)&Ps[(ty * 4 + i) * PP + tx * 4] =
                make_float4(s_acc[i][0], s_acc[i][1], s_acc[i][2], s_acc[i][3]);
        }
        __syncthreads();   // K reads + P writes complete

        // load V tile into the same buffer
        for (int idx = tid; idx < FBN * (HDIM / 4); idx += 256) {
            int r = idx >> 5, d4 = (idx & 31) << 2;
            *(float4*)&KVs[r * KP + d4] =
                *(const float4*)&V[base + (size_t)(kt * FBN + r) * DMODEL + d4];
        }
        __syncthreads();

        // O += P @ V
        for (int c = 0; c < FBN; c++) {
            float4 v0 = *(const float4*)&KVs[c * KP + tx * 8];
            float4 v1 = *(const float4*)&KVs[c * KP + tx * 8 + 4];
#pragma unroll
            for (int i = 0; i < 4; i++) {
                float pv = Ps[(ty * 4 + i) * PP + c];
                Oc[i][0] = fmaf(pv, v0.x, Oc[i][0]);
                Oc[i][1] = fmaf(pv, v0.y, Oc[i][1]);
                Oc[i][2] = fmaf(pv, v0.z, Oc[i][2]);
                Oc[i][3] = fmaf(pv, v0.w, Oc[i][3]);
                Oc[i][4] = fmaf(pv, v1.x, Oc[i][4]);
                Oc[i][5] = fmaf(pv, v1.y, Oc[i][5]);
                Oc[i][6] = fmaf(pv, v1.z, Oc[i][6]);
                Oc[i][7] = fmaf(pv, v1.w, Oc[i][7]);
            }
        }
    }

    // finalize and store
#pragma unroll
    for (int i = 0; i < 4; i++) {
        float inv = 1.0f / li[i];
        size_t row = base + (size_t)(q0 + ty * 4 + i) * DMODEL + tx * 8;
        float4 o0 = make_float4(Oc[i][0] * inv, Oc[i][1] * inv,
                                Oc[i][2] * inv, Oc[i][3] * inv);
        float4 o1 = make_float4(Oc[i][4] * inv, Oc[i][5] * inv,
                                Oc[i][6] * inv, Oc[i][7] * inv);
        *(float4*)&O[row]     = o0;
        *(float4*)&O[row + 4] = o1;
    }
}

// ==========================================================================
// launch
// ==========================================================================
extern "C" void kernel_launch(void* const* d_in, const int* in_sizes, int n_in,
                              void* d_out, int out_size)
{
    const float* x  = (const float*)d_in[0];
    // d_in[1] = mask (always causal tril; handled analytically)
    const float* Wq = (const float*)d_in[2];
    const float* bq = (const float*)d_in[3];
    const float* Wk = (const float*)d_in[4];
    const float* bk = (const float*)d_in[5];
    const float* Wv = (const float*)d_in[6];
    const float* bv = (const float*)d_in[7];
    const float* Wo = (const float*)d_in[8];
    const float* bo = (const float*)d_in[9];
    float* out = (float*)d_out;

    float *Qb, *Kb, *Vb, *Ab;
    cudaGetSymbolAddress((void**)&Qb, g_Q);
    cudaGetSymbolAddress((void**)&Kb, g_K);
    cudaGetSymbolAddress((void**)&Vb, g_V);
    cudaGetSymbolAddress((void**)&Ab, g_A);

    dim3 ggrid(DMODEL / GBN, MTOK / GBM);   // (16, 32)

    gemm_xwT_bias<<<ggrid, 256>>>(x, Wq, bq, Qb, MTOK, DMODEL, DMODEL);
    gemm_xwT_bias<<<ggrid, 256>>>(x, Wk, bk, Kb, MTOK, DMODEL, DMODEL);
    gemm_xwT_bias<<<ggrid, 256>>>(x, Wv, bv, Vb, MTOK, DMODEL, DMODEL);

    int pairs = MTOK * NHEADS * (HDIM / 2);
    rope_kernel<<<(pairs + 255) / 256, 256>>>(Qb, Kb);

    cudaFuncSetAttribute(flash_attn,
                         cudaFuncAttributeMaxDynamicSharedMemorySize,
                         FLASH_SMEM);
    dim3 fgrid(SEQ / FBM, NHEADS, BATCH);   // (32, 16, 2)
    flash_attn<<<fgrid, 256, FLASH_SMEM>>>(Qb, Kb, Vb, Ab);

    gemm_xwT_bias<<<ggrid, 256>>>(Ab, Wo, bo, out, MTOK, DMODEL, DMODEL);
}

// round 5
// speedup vs baseline: 1.7843x; 1.7843x over previous
#include <cuda_runtime.h>
#include <math.h>

// Problem constants
#define BATCH   2
#define SEQ     2048
#define DMODEL  2048
#define NHEADS  16
#define HDIM    128
#define MTOK    (BATCH*SEQ)   // 4096 tokens

// -------------------- scratch (device globals: no cudaMalloc allowed) -----
__device__ float g_Q[(size_t)MTOK*DMODEL];
__device__ float g_K[(size_t)MTOK*DMODEL];
__device__ float g_V[(size_t)MTOK*DMODEL];
__device__ float g_A[(size_t)MTOK*DMODEL];

// ==========================================================================
// TF32 tensor-core GEMM:  C[M,N] = A[M,K] @ W[N,K]^T + bias[N]
// 128x128x32 CTA tile, 256 threads (8 warps in 2x4), 64x32 warp tile,
// mma.sync.m16n8k8.tf32, cp.async double-buffered smem, pitch-36 padding
// (conflict-free fragment LDS).
// ==========================================================================
#define TBM 128
#define TBN 128
#define TBK 32
#define SP  36                 // smem row pitch in floats (32 + 4 pad)
#define GSTRIDE (TBM * SP)     // floats per tile buffer

__device__ __forceinline__ unsigned f2tf(float f) {
    unsigned u;
    asm("cvt.rna.tf32.f32 %0, %1;" : "=r"(u) : "f"(f));
    return u;
}

__device__ __forceinline__ void cp16(unsigned dst, const void* src) {
    asm volatile("cp.async.cg.shared.global [%0], [%1], 16;\n"
                 :: "r"(dst), "l"(src));
}

#define MMA_TF32(d, a, b)                                                  \
    asm volatile("mma.sync.aligned.m16n8k8.row.col.f32.tf32.tf32.f32 "     \
                 "{%0,%1,%2,%3}, {%4,%5,%6,%7}, {%8,%9}, {%0,%1,%2,%3};"   \
                 : "+f"(d[0]), "+f"(d[1]), "+f"(d[2]), "+f"(d[3])          \
                 : "r"(a[0]), "r"(a[1]), "r"(a[2]), "r"(a[3]),             \
                   "r"(b[0]), "r"(b[1]))

__global__ __launch_bounds__(256, 2)
void gemm_tf32_xwT_bias(const float* __restrict__ A, const float* __restrict__ W,
                        const float* __restrict__ bias, float* __restrict__ C,
                        int M, int N, int K)
{
    extern __shared__ float sm[];
    // stage s: A tile at sm + s*2*GSTRIDE, W tile at +GSTRIDE
    const int tid  = threadIdx.x;
    const int wid  = tid >> 5;
    const int lane = tid & 31;
    const int warp_m = wid >> 2;   // 0..1
    const int warp_n = wid & 3;    // 0..3
    const int gid = lane >> 2;     // 0..7
    const int tig = lane & 3;      // 0..3
    const int m0 = blockIdx.y * TBM;
    const int n0 = blockIdx.x * TBN;

    unsigned sbase;
    {
        unsigned long long p;
        asm("{ .reg .u64 t; cvta.to.shared.u64 t, %1; mov.u64 %0, t; }"
            : "=l"(p) : "l"(sm));
        sbase = (unsigned)p;
    }

    float acc[4][4][4];
#pragma unroll
    for (int mt = 0; mt < 4; mt++)
#pragma unroll
        for (int nt = 0; nt < 4; nt++)
#pragma unroll
            for (int r = 0; r < 4; r++) acc[mt][nt][r] = 0.0f;

    const int KT = K / TBK;   // 64

    // ---- copy helper: stage s, k-offset k0 ------------------------------
    auto copy_tile = [&](int s, int k0) {
        unsigned aBase = sbase + (unsigned)(s * 2 * GSTRIDE) * 4u;
        unsigned bBase = aBase + (unsigned)GSTRIDE * 4u;
#pragma unroll
        for (int r = 0; r < 4; r++) {
            int lin = tid + 256 * r;        // 0..1023
            int mm = lin >> 3;              // 0..127
            int jj = lin & 7;               // 0..7
            unsigned off = (unsigned)(mm * SP + jj * 4) * 4u;
            cp16(aBase + off, &A[(size_t)(m0 + mm) * K + k0 + jj * 4]);
            cp16(bBase + off, &W[(size_t)(n0 + mm) * K + k0 + jj * 4]);
        }
    };

    // prologue: stage 0
    copy_tile(0, 0);
    asm volatile("cp.async.commit_group;\n");

    for (int kt = 0; kt < KT; kt++) {
        int cur = kt & 1;
        if (kt + 1 < KT) copy_tile(cur ^ 1, (kt + 1) * TBK);
        asm volatile("cp.async.commit_group;\n");
        asm volatile("cp.async.wait_group 1;\n");
        __syncthreads();

        const float* As = sm + cur * 2 * GSTRIDE;
        const float* Bs = As + GSTRIDE;
        const int mrow0 = warp_m * 64;
        const int ncol0 = warp_n * 32;

#pragma unroll
        for (int ks = 0; ks < 4; ks++) {
            const int k = ks * 8;
            unsigned a[4][4], b[4][2];
#pragma unroll
            for (int mt = 0; mt < 4; mt++) {
                int rb = mrow0 + mt * 16;
                a[mt][0] = f2tf(As[(rb + gid) * SP + k + tig]);
                a[mt][1] = f2tf(As[(rb + gid + 8) * SP + k + tig]);
                a[mt][2] = f2tf(As[(rb + gid) * SP + k + tig + 4]);
                a[mt][3] = f2tf(As[(rb + gid + 8) * SP + k + tig + 4]);
            }
#pragma unroll
            for (int nt = 0; nt < 4; nt++) {
                int nb = ncol0 + nt * 8;
                b[nt][0] = f2tf(Bs[(nb + gid) * SP + k + tig]);
                b[nt][1] = f2tf(Bs[(nb + gid) * SP + k + tig + 4]);
            }
#pragma unroll
            for (int mt = 0; mt < 4; mt++)
#pragma unroll
                for (int nt = 0; nt < 4; nt++)
                    MMA_TF32(acc[mt][nt], a[mt], b[nt]);
        }
        __syncthreads();
    }

    // epilogue: bias add + store (float2 per c-pair)
#pragma unroll
    for (int mt = 0; mt < 4; mt++) {
        int r0 = m0 + warp_m * 64 + mt * 16 + gid;
#pragma unroll
        for (int nt = 0; nt < 4; nt++) {
            int c0 = n0 + warp_n * 32 + nt * 8 + tig * 2;
            float2 bv = *(const float2*)&bias[c0];
            float2 lo = make_float2(acc[mt][nt][0] + bv.x, acc[mt][nt][1] + bv.y);
            float2 hi = make_float2(acc[mt][nt][2] + bv.x, acc[mt][nt][3] + bv.y);
            *(float2*)&C[(size_t)r0 * N + c0]       = lo;
            *(float2*)&C[(size_t)(r0 + 8) * N + c0] = hi;
        }
    }
}

#define GEMM_SMEM (4 * GSTRIDE * 4)   // 73728 bytes

// ==========================================================================
// RoPE (in-place on Q and K, token-major [B*S][DMODEL])
// ==========================================================================
__global__ void rope_kernel(float* __restrict__ Q, float* __restrict__ K)
{
    int p = blockIdx.x * blockDim.x + threadIdx.x;
    const int total = MTOK * NHEADS * (HDIM / 2);
    if (p >= total) return;
    int d = p & 63;
    int h = (p >> 6) & (NHEADS - 1);
    int m = p >> 10;               // token index 0..4095
    int s = m & (SEQ - 1);         // position within sequence

    float inv_freq = powf(10000.0f, -(float)(2 * d) / (float)HDIM);
    float ang = (float)s * inv_freq;
    float sn, cs;
    sincosf(ang, &sn, &cs);

    size_t i1 = (size_t)m * DMODEL + h * HDIM + d;
    size_t i2 = i1 + 64;
    float q1 = Q[i1], q2 = Q[i2];
    Q[i1] = q1 * cs - q2 * sn;
    Q[i2] = q1 * sn + q2 * cs;
    float k1 = K[i1], k2 = K[i2];
    K[i1] = k1 * cs - k2 * sn;
    K[i2] = k1 * sn + k2 * cs;
}

// ==========================================================================
// Flash attention (fp32, causal), 64x64 tiles, online softmax. (unchanged)
// ==========================================================================
#define FBM 64
#define FBN 64
#define QP  132
#define KP  132
#define PP  68
#define FLASH_SMEM (((FBM*QP) + (FBN*KP) + (FBM*PP)) * 4)

__global__ __launch_bounds__(256, 2)
void flash_attn(const float* __restrict__ Q, const float* __restrict__ K,
                const float* __restrict__ V, float* __restrict__ O)
{
    extern __shared__ float sm[];
    float* Qs  = sm;
    float* KVs = sm + FBM * QP;
    float* Ps  = KVs + FBN * KP;

    const int tid = threadIdx.x;
    const int ty = tid >> 4, tx = tid & 15;
    const int qt = blockIdx.x, h = blockIdx.y, b = blockIdx.z;
    const int q0 = qt * FBM;
    const float scale = rsqrtf((float)HDIM);

    const size_t base = (size_t)b * SEQ * DMODEL + (size_t)h * HDIM;

    for (int idx = tid; idx < FBM * (HDIM / 4); idx += 256) {
        int r  = idx >> 5;
        int d4 = (idx & 31) << 2;
        float4 v = *(const float4*)&Q[base + (size_t)(q0 + r) * DMODEL + d4];
        v.x *= scale; v.y *= scale; v.z *= scale; v.w *= scale;
        *(float4*)&Qs[r * QP + d4] = v;
    }

    float mi[4], li[4], Oc[4][8];
#pragma unroll
    for (int i = 0; i < 4; i++) {
        mi[i] = -INFINITY; li[i] = 0.0f;
#pragma unroll
        for (int j = 0; j < 8; j++) Oc[i][j] = 0.0f;
    }

    for (int kt = 0; kt <= qt; kt++) {
        __syncthreads();
        for (int idx = tid; idx < FBN * (HDIM / 4); idx += 256) {
            int r = idx >> 5, d4 = (idx & 31) << 2;
            *(float4*)&KVs[r * KP + d4] =
                *(const float4*)&K[base + (size_t)(kt * FBN + r) * DMODEL + d4];
        }
        __syncthreads();

        float s_acc[4][4];
#pragma unroll
        for (int i = 0; i < 4; i++)
#pragma unroll
            for (int j = 0; j < 4; j++) s_acc[i][j] = 0.0f;

        for (int k4 = 0; k4 < HDIM; k4 += 4) {
            float4 a[4], bb[4];
#pragma unroll
            for (int i = 0; i < 4; i++)
                a[i] = *(const float4*)&Qs[(ty * 4 + i) * QP + k4];
#pragma unroll
            for (int j = 0; j < 4; j++)
                bb[j] = *(const float4*)&KVs[(tx * 4 + j) * KP + k4];
#pragma unroll
            for (int i = 0; i < 4; i++)
#pragma unroll
                for (int j = 0; j < 4; j++)
                    s_acc[i][j] += a[i].x * bb[j].x + a[i].y * bb[j].y
                                 + a[i].z * bb[j].z + a[i].w * bb[j].w;
        }

        if (kt == qt) {
#pragma unroll
            for (int i = 0; i < 4; i++)
#pragma unroll
                for (int j = 0; j < 4; j++)
                    if (tx * 4 + j > ty * 4 + i) s_acc[i][j] = -INFINITY;
        }

#pragma unroll
        for (int i = 0; i < 4; i++) {
            float rmax = fmaxf(fmaxf(s_acc[i][0], s_acc[i][1]),
                               fmaxf(s_acc[i][2], s_acc[i][3]));
#pragma unroll
            for (int off = 8; off > 0; off >>= 1)
                rmax = fmaxf(rmax, __shfl_xor_sync(0xffffffffu, rmax, off));
            float mnew = fmaxf(mi[i], rmax);
            float corr = __expf(mi[i] - mnew);
            float rs = 0.0f;
#pragma unroll
            for (int j = 0; j < 4; j++) {
                float pv = __expf(s_acc[i][j] - mnew);
                s_acc[i][j] = pv;
                rs += pv;
            }
#pragma unroll
            for (int off = 8; off > 0; off >>= 1)
                rs += __shfl_xor_sync(0xffffffffu, rs, off);
            li[i] = li[i] * corr + rs;
            mi[i] = mnew;
#pragma unroll
            for (int jj = 0; jj < 8; jj++) Oc[i][jj] *= corr;
            *(float4*)&Ps[(ty * 4 + i) * PP + tx * 4] =
                make_float4(s_acc[i][0], s_acc[i][1], s_acc[i][2], s_acc[i][3]);
        }
        __syncthreads();

        for (int idx = tid; idx < FBN * (HDIM / 4); idx += 256) {
            int r = idx >> 5, d4 = (idx & 31) << 2;
            *(float4*)&KVs[r * KP + d4] =
                *(const float4*)&V[base + (size_t)(kt * FBN + r) * DMODEL + d4];
        }
        __syncthreads();

        for (int c = 0; c < FBN; c++) {
            float4 v0 = *(const float4*)&KVs[c * KP + tx * 8];
            float4 v1 = *(const float4*)&KVs[c * KP + tx * 8 + 4];
#pragma unroll
            for (int i = 0; i < 4; i++) {
                float pv = Ps[(ty * 4 + i) * PP + c];
                Oc[i][0] = fmaf(pv, v0.x, Oc[i][0]);
                Oc[i][1] = fmaf(pv, v0.y, Oc[i][1]);
                Oc[i][2] = fmaf(pv, v0.z, Oc[i][2]);
                Oc[i][3] = fmaf(pv, v0.w, Oc[i][3]);
                Oc[i][4] = fmaf(pv, v1.x, Oc[i][4]);
                Oc[i][5] = fmaf(pv, v1.y, Oc[i][5]);
                Oc[i][6] = fmaf(pv, v1.z, Oc[i][6]);
                Oc[i][7] = fmaf(pv, v1.w, Oc[i][7]);
            }
        }
    }

#pragma unroll
    for (int i = 0; i < 4; i++) {
        float inv = 1.0f / li[i];
        size_t row = base + (size_t)(q0 + ty * 4 + i) * DMODEL + tx * 8;
        float4 o0 = make_float4(Oc[i][0] * inv, Oc[i][1] * inv,
                                Oc[i][2] * inv, Oc[i][3] * inv);
        float4 o1 = make_float4(Oc[i][4] * inv, Oc[i][5] * inv,
                                Oc[i][6] * inv, Oc[i][7] * inv);
        *(float4*)&O[row]     = o0;
        *(float4*)&O[row + 4] = o1;
    }
}

// ==========================================================================
// launch
// ==========================================================================
extern "C" void kernel_launch(void* const* d_in, const int* in_sizes, int n_in,
                              void* d_out, int out_size)
{
    const float* x  = (const float*)d_in[0];
    // d_in[1] = mask (always causal tril; handled analytically)
    const float* Wq = (const float*)d_in[2];
    const float* bq = (const float*)d_in[3];
    const float* Wk = (const float*)d_in[4];
    const float* bk = (const float*)d_in[5];
    const float* Wv = (const float*)d_in[6];
    const float* bv = (const float*)d_in[7];
    const float* Wo = (const float*)d_in[8];
    const float* bo = (const float*)d_in[9];
    float* out = (float*)d_out;

    float *Qb, *Kb, *Vb, *Ab;
    cudaGetSymbolAddress((void**)&Qb, g_Q);
    cudaGetSymbolAddress((void**)&Kb, g_K);
    cudaGetSymbolAddress((void**)&Vb, g_V);
    cudaGetSymbolAddress((void**)&Ab, g_A);

    cudaFuncSetAttribute(gemm_tf32_xwT_bias,
                         cudaFuncAttributeMaxDynamicSharedMemorySize,
                         GEMM_SMEM);
    cudaFuncSetAttribute(flash_attn,
                         cudaFuncAttributeMaxDynamicSharedMemorySize,
                         FLASH_SMEM);

    dim3 ggrid(DMODEL / TBN, MTOK / TBM);   // (16, 32)

    gemm_tf32_xwT_bias<<<ggrid, 256, GEMM_SMEM>>>(x, Wq, bq, Qb, MTOK, DMODEL, DMODEL);
    gemm_tf32_xwT_bias<<<ggrid, 256, GEMM_SMEM>>>(x, Wk, bk, Kb, MTOK, DMODEL, DMODEL);
    gemm_tf32_xwT_bias<<<ggrid, 256, GEMM_SMEM>>>(x, Wv, bv, Vb, MTOK, DMODEL, DMODEL);

    int pairs = MTOK * NHEADS * (HDIM / 2);
    rope_kernel<<<(pairs + 255) / 256, 256>>>(Qb, Kb);

    dim3 fgrid(SEQ / FBM, NHEADS, BATCH);   // (32, 16, 2)
    flash_attn<<<fgrid, 256, FLASH_SMEM>>>(Qb, Kb, Vb, Ab);

    gemm_tf32_xwT_bias<<<ggrid, 256, GEMM_SMEM>>>(Ab, Wo, bo, out, MTOK, DMODEL, DMODEL);
}

// round 6
// speedup vs baseline: 3.4594x; 1.9387x over previous
#include <cuda_runtime.h>
#include <math.h>

// Problem constants
#define BATCH   2
#define SEQ     2048
#define DMODEL  2048
#define NHEADS  16
#define HDIM    128
#define MTOK    (BATCH*SEQ)   // 4096 tokens

// -------------------- scratch (device globals: no cudaMalloc allowed) -----
__device__ float g_Q[(size_t)MTOK*DMODEL];
__device__ float g_K[(size_t)MTOK*DMODEL];
__device__ float g_V[(size_t)MTOK*DMODEL];
__device__ float g_A[(size_t)MTOK*DMODEL];

// -------------------- tf32 helpers ----------------------------------------
__device__ __forceinline__ unsigned f2tf(float f) {
    unsigned u;
    asm("cvt.rna.tf32.f32 %0, %1;" : "=r"(u) : "f"(f));
    return u;
}
__device__ __forceinline__ float f2tf_f(float f) {
    return __uint_as_float(f2tf(f));
}

__device__ __forceinline__ void cp16(unsigned dst, const void* src) {
    asm volatile("cp.async.cg.shared.global [%0], [%1], 16;\n"
                 :: "r"(dst), "l"(src));
}

#define MMA_TF32(d, a, b)                                                  \
    asm volatile("mma.sync.aligned.m16n8k8.row.col.f32.tf32.tf32.f32 "     \
                 "{%0,%1,%2,%3}, {%4,%5,%6,%7}, {%8,%9}, {%0,%1,%2,%3};"   \
                 : "+f"(d[0]), "+f"(d[1]), "+f"(d[2]), "+f"(d[3])          \
                 : "r"(a[0]), "r"(a[1]), "r"(a[2]), "r"(a[3]),             \
                   "r"(b[0]), "r"(b[1]))

// ==========================================================================
// TF32 tensor-core GEMM:  C[M,N] = A[M,K] @ W[N,K]^T + bias[N]  (unchanged)
// ==========================================================================
#define TBM 128
#define TBN 128
#define TBK 32
#define SP  36
#define GSTRIDE (TBM * SP)

__global__ __launch_bounds__(256, 2)
void gemm_tf32_xwT_bias(const float* __restrict__ A, const float* __restrict__ W,
                        const float* __restrict__ bias, float* __restrict__ C,
                        int M, int N, int K)
{
    extern __shared__ float sm[];
    const int tid  = threadIdx.x;
    const int wid  = tid >> 5;
    const int lane = tid & 31;
    const int warp_m = wid >> 2;
    const int warp_n = wid & 3;
    const int gid = lane >> 2;
    const int tig = lane & 3;
    const int m0 = blockIdx.y * TBM;
    const int n0 = blockIdx.x * TBN;

    unsigned sbase;
    {
        unsigned long long p;
        asm("{ .reg .u64 t; cvta.to.shared.u64 t, %1; mov.u64 %0, t; }"
            : "=l"(p) : "l"(sm));
        sbase = (unsigned)p;
    }

    float acc[4][4][4];
#pragma unroll
    for (int mt = 0; mt < 4; mt++)
#pragma unroll
        for (int nt = 0; nt < 4; nt++)
#pragma unroll
            for (int r = 0; r < 4; r++) acc[mt][nt][r] = 0.0f;

    const int KT = K / TBK;

    auto copy_tile = [&](int s, int k0) {
        unsigned aBase = sbase + (unsigned)(s * 2 * GSTRIDE) * 4u;
        unsigned bBase = aBase + (unsigned)GSTRIDE * 4u;
#pragma unroll
        for (int r = 0; r < 4; r++) {
            int lin = tid + 256 * r;
            int mm = lin >> 3;
            int jj = lin & 7;
            unsigned off = (unsigned)(mm * SP + jj * 4) * 4u;
            cp16(aBase + off, &A[(size_t)(m0 + mm) * K + k0 + jj * 4]);
            cp16(bBase + off, &W[(size_t)(n0 + mm) * K + k0 + jj * 4]);
        }
    };

    copy_tile(0, 0);
    asm volatile("cp.async.commit_group;\n");

    for (int kt = 0; kt < KT; kt++) {
        int cur = kt & 1;
        if (kt + 1 < KT) copy_tile(cur ^ 1, (kt + 1) * TBK);
        asm volatile("cp.async.commit_group;\n");
        asm volatile("cp.async.wait_group 1;\n");
        __syncthreads();

        const float* As = sm + cur * 2 * GSTRIDE;
        const float* Bs = As + GSTRIDE;
        const int mrow0 = warp_m * 64;
        const int ncol0 = warp_n * 32;

#pragma unroll
        for (int ks = 0; ks < 4; ks++) {
            const int k = ks * 8;
            unsigned a[4][4], b[4][2];
#pragma unroll
            for (int mt = 0; mt < 4; mt++) {
                int rb = mrow0 + mt * 16;
                a[mt][0] = f2tf(As[(rb + gid) * SP + k + tig]);
                a[mt][1] = f2tf(As[(rb + gid + 8) * SP + k + tig]);
                a[mt][2] = f2tf(As[(rb + gid) * SP + k + tig + 4]);
                a[mt][3] = f2tf(As[(rb + gid + 8) * SP + k + tig + 4]);
            }
#pragma unroll
            for (int nt = 0; nt < 4; nt++) {
                int nb = ncol0 + nt * 8;
                b[nt][0] = f2tf(Bs[(nb + gid) * SP + k + tig]);
                b[nt][1] = f2tf(Bs[(nb + gid) * SP + k + tig + 4]);
            }
#pragma unroll
            for (int mt = 0; mt < 4; mt++)
#pragma unroll
                for (int nt = 0; nt < 4; nt++)
                    MMA_TF32(acc[mt][nt], a[mt], b[nt]);
        }
        __syncthreads();
    }

#pragma unroll
    for (int mt = 0; mt < 4; mt++) {
        int r0 = m0 + warp_m * 64 + mt * 16 + gid;
#pragma unroll
        for (int nt = 0; nt < 4; nt++) {
            int c0 = n0 + warp_n * 32 + nt * 8 + tig * 2;
            float2 bv = *(const float2*)&bias[c0];
            float2 lo = make_float2(acc[mt][nt][0] + bv.x, acc[mt][nt][1] + bv.y);
            float2 hi = make_float2(acc[mt][nt][2] + bv.x, acc[mt][nt][3] + bv.y);
            *(float2*)&C[(size_t)r0 * N + c0]       = lo;
            *(float2*)&C[(size_t)(r0 + 8) * N + c0] = hi;
        }
    }
}

#define GEMM_SMEM (4 * GSTRIDE * 4)

// ==========================================================================
// RoPE (unchanged)
// ==========================================================================
__global__ void rope_kernel(float* __restrict__ Q, float* __restrict__ K)
{
    int p = blockIdx.x * blockDim.x + threadIdx.x;
    const int total = MTOK * NHEADS * (HDIM / 2);
    if (p >= total) return;
    int d = p & 63;
    int h = (p >> 6) & (NHEADS - 1);
    int m = p >> 10;
    int s = m & (SEQ - 1);

    float inv_freq = powf(10000.0f, -(float)(2 * d) / (float)HDIM);
    float ang = (float)s * inv_freq;
    float sn, cs;
    sincosf(ang, &sn, &cs);

    size_t i1 = (size_t)m * DMODEL + h * HDIM + d;
    size_t i2 = i1 + 64;
    float q1 = Q[i1], q2 = Q[i2];
    Q[i1] = q1 * cs - q2 * sn;
    Q[i2] = q1 * sn + q2 * cs;
    float k1 = K[i1], k2 = K[i2];
    K[i1] = k1 * cs - k2 * sn;
    K[i2] = k1 * sn + k2 * cs;
}

// ==========================================================================
// Flash attention with tf32 tensor cores (causal, online softmax).
// CTA: 64 q-rows; iterates 64-key tiles. 256 threads = 8 warps.
// Warp (wm=wid>>1, wn=wid&1):
//   QK phase: warp tile = 16 q-rows (wm*16) x 32 keys (wn*32)
//   PV phase: warp tile = 16 q-rows (wm*16) x 64 dims (wn*64)
// Q/K/V staged in smem as tf32; P staged through smem (tf32 after exp).
// Per-row m/l/corr state in smem; softmax pass is warp-per-8-rows.
// ==========================================================================
#define FP 132          // Q/K/V smem pitch (floats)
#define PSP 68          // P smem pitch
#define FA_SMEM ((3 * 64 * FP + 64 * PSP + 3 * 64) * 4)

__global__ __launch_bounds__(256, 1)
void flash_attn_tc(const float* __restrict__ Q, const float* __restrict__ K,
                   const float* __restrict__ V, float* __restrict__ O)
{
    extern __shared__ float sm[];
    float* Qs = sm;                 // [64][FP]
    float* Ks = Qs + 64 * FP;       // [64][FP]
    float* Vs = Ks + 64 * FP;       // [64][FP]
    float* Ps = Vs + 64 * FP;       // [64][PSP]
    float* Ms = Ps + 64 * PSP;      // [64] running max
    float* Ls = Ms + 64;            // [64] running sum
    float* Cs = Ls + 64;            // [64] correction

    const int tid  = threadIdx.x;
    const int wid  = tid >> 5;
    const int lane = tid & 31;
    const int gid  = lane >> 2;     // 0..7
    const int tig  = lane & 3;      // 0..3
    const int wm   = wid >> 1;      // 0..3
    const int wn   = wid & 1;       // 0..1

    const int qt = blockIdx.x, h = blockIdx.y, b = blockIdx.z;
    const int q0 = qt * 64;
    const float scale = rsqrtf((float)HDIM);
    const size_t base = (size_t)b * SEQ * DMODEL + (size_t)h * HDIM;

    // load Q tile (scale + tf32 convert)
    for (int idx = tid; idx < 64 * 32; idx += 256) {
        int r = idx >> 5, c4 = (idx & 31) << 2;
        float4 v = *(const float4*)&Q[base + (size_t)(q0 + r) * DMODEL + c4];
        Qs[r * FP + c4 + 0] = f2tf_f(v.x * scale);
        Qs[r * FP + c4 + 1] = f2tf_f(v.y * scale);
        Qs[r * FP + c4 + 2] = f2tf_f(v.z * scale);
        Qs[r * FP + c4 + 3] = f2tf_f(v.w * scale);
    }
    if (tid < 64) { Ms[tid] = -INFINITY; Ls[tid] = 0.0f; }

    // O accumulators: 8 n-tiles x 4 regs (rows gid / gid+8, cols 2tig/2tig+1)
    float o[8][4];
#pragma unroll
    for (int nt = 0; nt < 8; nt++)
#pragma unroll
        for (int r = 0; r < 4; r++) o[nt][r] = 0.0f;

    for (int kt = 0; kt <= qt; kt++) {
        __syncthreads();   // previous PV reads of Vs/Ps complete
        // load K, V tiles (tf32 convert)
        for (int idx = tid; idx < 64 * 32; idx += 256) {
            int r = idx >> 5, c4 = (idx & 31) << 2;
            size_t gofs = base + (size_t)(kt * 64 + r) * DMODEL + c4;
            float4 kv = *(const float4*)&K[gofs];
            Ks[r * FP + c4 + 0] = f2tf_f(kv.x);
            Ks[r * FP + c4 + 1] = f2tf_f(kv.y);
            Ks[r * FP + c4 + 2] = f2tf_f(kv.z);
            Ks[r * FP + c4 + 3] = f2tf_f(kv.w);
            float4 vv = *(const float4*)&V[gofs];
            Vs[r * FP + c4 + 0] = f2tf_f(vv.x);
            Vs[r * FP + c4 + 1] = f2tf_f(vv.y);
            Vs[r * FP + c4 + 2] = f2tf_f(vv.z);
            Vs[r * FP + c4 + 3] = f2tf_f(vv.w);
        }
        __syncthreads();

        // ---- S = Q @ K^T : warp computes 16x32 ----
        float s[4][4];
#pragma unroll
        for (int nt = 0; nt < 4; nt++)
#pragma unroll
            for (int r = 0; r < 4; r++) s[nt][r] = 0.0f;

        const int rb = wm * 16;
#pragma unroll
        for (int ks = 0; ks < 16; ks++) {
            const int k0 = ks * 8;
            unsigned a[4];
            a[0] = __float_as_uint(Qs[(rb + gid) * FP + k0 + tig]);
            a[1] = __float_as_uint(Qs[(rb + gid + 8) * FP + k0 + tig]);
            a[2] = __float_as_uint(Qs[(rb + gid) * FP + k0 + tig + 4]);
            a[3] = __float_as_uint(Qs[(rb + gid + 8) * FP + k0 + tig + 4]);
#pragma unroll
            for (int nt = 0; nt < 4; nt++) {
                int nidx = wn * 32 + nt * 8 + gid;
                unsigned bb[2];
                bb[0] = __float_as_uint(Ks[nidx * FP + k0 + tig]);
                bb[1] = __float_as_uint(Ks[nidx * FP + k0 + tig + 4]);
                MMA_TF32(s[nt], a, bb);
            }
        }

        // causal mask on diagonal tile
        if (kt == qt) {
#pragma unroll
            for (int nt = 0; nt < 4; nt++) {
                int col = wn * 32 + nt * 8 + 2 * tig;
                int r0 = rb + gid, r1 = rb + gid + 8;
                if (col     > r0) s[nt][0] = -INFINITY;
                if (col + 1 > r0) s[nt][1] = -INFINITY;
                if (col     > r1) s[nt][2] = -INFINITY;
                if (col + 1 > r1) s[nt][3] = -INFINITY;
            }
        }

        // stage S to smem
#pragma unroll
        for (int nt = 0; nt < 4; nt++) {
            int c = wn * 32 + nt * 8 + 2 * tig;
            *(float2*)&Ps[(rb + gid) * PSP + c]     = make_float2(s[nt][0], s[nt][1]);
            *(float2*)&Ps[(rb + gid + 8) * PSP + c] = make_float2(s[nt][2], s[nt][3]);
        }
        __syncthreads();

        // ---- softmax pass: warp handles rows [wid*8, wid*8+8), 4 lanes/row
        {
            int row = wid * 8 + gid;
            int c0 = tig * 16;
            float4 v0 = *(const float4*)&Ps[row * PSP + c0];
            float4 v1 = *(const float4*)&Ps[row * PSP + c0 + 4];
            float4 v2 = *(const float4*)&Ps[row * PSP + c0 + 8];
            float4 v3 = *(const float4*)&Ps[row * PSP + c0 + 12];
            float tmax = fmaxf(fmaxf(fmaxf(v0.x, v0.y), fmaxf(v0.z, v0.w)),
                               fmaxf(fmaxf(v1.x, v1.y), fmaxf(v1.z, v1.w)));
            tmax = fmaxf(tmax,
                   fmaxf(fmaxf(fmaxf(v2.x, v2.y), fmaxf(v2.z, v2.w)),
                         fmaxf(fmaxf(v3.x, v3.y), fmaxf(v3.z, v3.w))));
            tmax = fmaxf(tmax, __shfl_xor_sync(0xffffffffu, tmax, 1));
            tmax = fmaxf(tmax, __shfl_xor_sync(0xffffffffu, tmax, 2));
            float mold = Ms[row];
            float mnew = fmaxf(mold, tmax);
            float corr = __expf(mold - mnew);
            float sum = 0.0f;
            float p[16] = {v0.x, v0.y, v0.z, v0.w, v1.x, v1.y, v1.z, v1.w,
                           v2.x, v2.y, v2.z, v2.w, v3.x, v3.y, v3.z, v3.w};
#pragma unroll
            for (int j = 0; j < 16; j++) {
                float e = __expf(p[j] - mnew);
                sum += e;
                p[j] = f2tf_f(e);
            }
            *(float4*)&Ps[row * PSP + c0]      = make_float4(p[0], p[1], p[2], p[3]);
            *(float4*)&Ps[row * PSP + c0 + 4]  = make_float4(p[4], p[5], p[6], p[7]);
            *(float4*)&Ps[row * PSP + c0 + 8]  = make_float4(p[8], p[9], p[10], p[11]);
            *(float4*)&Ps[row * PSP + c0 + 12] = make_float4(p[12], p[13], p[14], p[15]);
            sum += __shfl_xor_sync(0xffffffffu, sum, 1);
            sum += __shfl_xor_sync(0xffffffffu, sum, 2);
            if (tig == 0) {
                Ms[row] = mnew;
                Ls[row] = Ls[row] * corr + sum;
                Cs[row] = corr;
            }
        }
        __syncthreads();

        // ---- O = O*corr + P @ V : warp computes 16 rows x 64 dims ----
        float cr0 = Cs[rb + gid];
        float cr1 = Cs[rb + gid + 8];
#pragma unroll
        for (int nt = 0; nt < 8; nt++) {
            o[nt][0] *= cr0; o[nt][1] *= cr0;
            o[nt][2] *= cr1; o[nt][3] *= cr1;
        }
#pragma unroll
        for (int ks = 0; ks < 8; ks++) {
            const int k0 = ks * 8;
            unsigned a[4];
            a[0] = __float_as_uint(Ps[(rb + gid) * PSP + k0 + tig]);
            a[1] = __float_as_uint(Ps[(rb + gid + 8) * PSP + k0 + tig]);
            a[2] = __float_as_uint(Ps[(rb + gid) * PSP + k0 + tig + 4]);
            a[3] = __float_as_uint(Ps[(rb + gid + 8) * PSP + k0 + tig + 4]);
#pragma unroll
            for (int nt = 0; nt < 8; nt++) {
                int n = wn * 64 + nt * 8 + gid;
                unsigned bb[2];
                bb[0] = __float_as_uint(Vs[(k0 + tig) * FP + n]);
                bb[1] = __float_as_uint(Vs[(k0 + tig + 4) * FP + n]);
                MMA_TF32(o[nt], a, bb);
            }
        }
    }

    // finalize: divide by l, store
    {
        const int rb = wm * 16;
        float inv0 = 1.0f / Ls[rb + gid];
        float inv1 = 1.0f / Ls[rb + gid + 8];
        size_t row0 = base + (size_t)(q0 + rb + gid) * DMODEL;
        size_t row1 = base + (size_t)(q0 + rb + gid + 8) * DMODEL;
#pragma unroll
        for (int nt = 0; nt < 8; nt++) {
            int c = wn * 64 + nt * 8 + 2 * tig;
            *(float2*)&O[row0 + c] = make_float2(o[nt][0] * inv0, o[nt][1] * inv0);
            *(float2*)&O[row1 + c] = make_float2(o[nt][2] * inv1, o[nt][3] * inv1);
        }
    }
}

// ==========================================================================
// launch
// ==========================================================================
extern "C" void kernel_launch(void* const* d_in, const int* in_sizes, int n_in,
                              void* d_out, int out_size)
{
    const float* x  = (const float*)d_in[0];
    // d_in[1] = mask (causal tril; handled analytically)
    const float* Wq = (const float*)d_in[2];
    const float* bq = (const float*)d_in[3];
    const float* Wk = (const float*)d_in[4];
    const float* bk = (const float*)d_in[5];
    const float* Wv = (const float*)d_in[6];
    const float* bv = (const float*)d_in[7];
    const float* Wo = (const float*)d_in[8];
    const float* bo = (const float*)d_in[9];
    float* out = (float*)d_out;

    float *Qb, *Kb, *Vb, *Ab;
    cudaGetSymbolAddress((void**)&Qb, g_Q);
    cudaGetSymbolAddress((void**)&Kb, g_K);
    cudaGetSymbolAddress((void**)&Vb, g_V);
    cudaGetSymbolAddress((void**)&Ab, g_A);

    cudaFuncSetAttribute(gemm_tf32_xwT_bias,
                         cudaFuncAttributeMaxDynamicSharedMemorySize, GEMM_SMEM);
    cudaFuncSetAttribute(flash_attn_tc,
                         cudaFuncAttributeMaxDynamicSharedMemorySize, FA_SMEM);

    dim3 ggrid(DMODEL / TBN, MTOK / TBM);   // (16, 32)

    gemm_tf32_xwT_bias<<<ggrid, 256, GEMM_SMEM>>>(x, Wq, bq, Qb, MTOK, DMODEL, DMODEL);
    gemm_tf32_xwT_bias<<<ggrid, 256, GEMM_SMEM>>>(x, Wk, bk, Kb, MTOK, DMODEL, DMODEL);
    gemm_tf32_xwT_bias<<<ggrid, 256, GEMM_SMEM>>>(x, Wv, bv, Vb, MTOK, DMODEL, DMODEL);

    int pairs = MTOK * NHEADS * (HDIM / 2);
    rope_kernel<<<(pairs + 255) / 256, 256>>>(Qb, Kb);

    dim3 fgrid(SEQ / 64, NHEADS, BATCH);    // (32, 16, 2)
    flash_attn_tc<<<fgrid, 256, FA_SMEM>>>(Qb, Kb, Vb, Ab);

    gemm_tf32_xwT_bias<<<ggrid, 256, GEMM_SMEM>>>(Ab, Wo, bo, out, MTOK, DMODEL, DMODEL);
}